// round 8
// baseline (speedup 1.0000x reference)
#include <cuda_runtime.h>
#include <cstdint>

#define N_NODES 250000
#define N_EDGES 4000000
#define NODE_F  4
#define HID     32
#define NN      50
#define NF      3
#define D_IN    9
#define OUT_C   53

// Scratch (device globals)
__device__ float  g_accC[N_NODES];                 // 1 MB
__device__ __align__(8) float2 g_accMS[N_NODES];   // 2 MB (tail nodes only)
__device__ float g_conc[N_NODES];
__device__ float g_S;
__device__ int   g_ei_is64;
__device__ float g_sc, g_sm, g_ss;                 // b2 . W*[4:36]
__device__ float g_uc[HID], g_um[HID], g_us[HID];  // W2 @ W*[4:36]
__device__ unsigned g_W1t[16 * HID];               // tf32 W1 padded to K=16 (row 9 = b1)

__device__ __forceinline__ float softplusf(float x) {
    return fmaxf(x, 0.0f) + log1pf(expf(-fabsf(x)));
}
__device__ __forceinline__ unsigned f2tf32(float f) {
    unsigned u; asm("cvt.rna.tf32.f32 %0, %1;" : "=r"(u) : "f"(f)); return u;
}
__device__ __forceinline__ void mma_tf32(float d[4],
                                         unsigned a0, unsigned a1, unsigned a2, unsigned a3,
                                         unsigned b0, unsigned b1) {
    asm("mma.sync.aligned.m16n8k8.row.col.f32.tf32.tf32.f32 "
        "{%0,%1,%2,%3}, {%4,%5,%6,%7}, {%8,%9}, {%0,%1,%2,%3};"
        : "+f"(d[0]), "+f"(d[1]), "+f"(d[2]), "+f"(d[3])
        : "r"(a0), "r"(a1), "r"(a2), "r"(a3), "r"(b0), "r"(b1));
}

// ---------------------------------------------------------------------------
// Kernel A: detect ei dtype + precompute projections + tf32 W1 (1 warp)
// ---------------------------------------------------------------------------
__global__ void prep_kernel(const int* __restrict__ ei32,
                            const float* __restrict__ W1,
                            const float* __restrict__ b1,
                            const float* __restrict__ W2,
                            const float* __restrict__ b2,
                            const float* __restrict__ Wc,
                            const float* __restrict__ Wmu,
                            const float* __restrict__ Wsig)
{
    const int k = threadIdx.x;  // 0..31 = hidden index / column
    if (k == 0) {
        int z = 0;
        #pragma unroll
        for (int i = 1; i < 64; i += 2) z |= ei32[i];
        g_ei_is64 = (z == 0) ? 1 : 0;
        g_S = 0.0f;
    }
    float uc = 0.f, um = 0.f, us = 0.f;
    #pragma unroll
    for (int m = 0; m < HID; m++) {
        const float w = W2[k * HID + m];
        uc = fmaf(w, Wc[NODE_F + m],   uc);
        um = fmaf(w, Wmu[NODE_F + m],  um);
        us = fmaf(w, Wsig[NODE_F + m], us);
    }
    g_uc[k] = uc; g_um[k] = um; g_us[k] = us;

    // tf32 W1, K padded to 16: rows 0..8 = W1, row 9 = b1 (input col 9 == 1), rows 10..15 = 0
    #pragma unroll
    for (int d = 0; d < D_IN; d++) g_W1t[d * HID + k] = f2tf32(W1[d * HID + k]);
    g_W1t[9 * HID + k] = f2tf32(b1[k]);
    #pragma unroll
    for (int d = 10; d < 16; d++) g_W1t[d * HID + k] = 0u;

    float pc = b2[k] * Wc[NODE_F + k];
    float pm = b2[k] * Wmu[NODE_F + k];
    float ps = b2[k] * Wsig[NODE_F + k];
    #pragma unroll
    for (int off = 16; off > 0; off >>= 1) {
        pc += __shfl_xor_sync(0xffffffffu, pc, off);
        pm += __shfl_xor_sync(0xffffffffu, pm, off);
        ps += __shfl_xor_sync(0xffffffffu, ps, off);
    }
    if (k == 0) { g_sc = pc; g_sm = pm; g_ss = ps; }
}

// ---------------------------------------------------------------------------
// Kernel B: zero accumulators
// ---------------------------------------------------------------------------
__global__ void zero_kernel() {
    const int i = blockIdx.x * blockDim.x + threadIdx.x;
    if (i < N_NODES) {
        g_accC[i] = 0.0f;
        if (i % NN >= NN - NF) g_accMS[i] = make_float2(0.f, 0.f);
    }
}

// ---------------------------------------------------------------------------
// Kernel C: tensor-core edge MLP. Warp handles 32 edges via tf32 m16n8k8 MMA.
// ---------------------------------------------------------------------------
#define ROWW 20   // padded SMEM row stride in words (80 B, conflict-free)

__global__ __launch_bounds__(256) void edge_kernel(
    const float* __restrict__ x,
    const void* __restrict__ ei_raw,
    const float* __restrict__ ea)
{
    __shared__ unsigned sA[8 * 32 * ROWW];         // 20 KB staging
    __shared__ float suc[HID], sum_[HID], sus[HID];

    const int tid  = threadIdx.x;
    const int warp = tid >> 5;
    const int lane = tid & 31;
    const int grp  = lane >> 2;   // 0..7
    const int tig  = lane & 3;    // 0..3

    if (tid < HID) {
        suc[tid]  = g_uc[tid];
        sum_[tid] = g_um[tid];
        sus[tid]  = g_us[tid];
    }

    // B fragments: B[kt][nt] for H = A[32x16] @ W1t[16x32]
    unsigned B0[2][4], B1[2][4];
    #pragma unroll
    for (int kt = 0; kt < 2; kt++)
        #pragma unroll
        for (int nt = 0; nt < 4; nt++) {
            B0[kt][nt] = g_W1t[(kt * 8 + tig)     * HID + nt * 8 + grp];
            B1[kt][nt] = g_W1t[(kt * 8 + tig + 4) * HID + nt * 8 + grp];
        }
    __syncthreads();

    const int base = (blockIdx.x * 8 + warp) * 32;
    const int e = base + lane;

    int r, c;
    if (g_ei_is64) {
        const long long* ei = (const long long*)ei_raw;
        r = (int)__ldg(ei + e);
        c = (int)__ldg(ei + N_EDGES + e);
    } else {
        const int* ei = (const int*)ei_raw;
        r = __ldg(ei + e);
        c = __ldg(ei + N_EDGES + e);
    }
    const float4* x4 = reinterpret_cast<const float4*>(x);
    const float4 xr = __ldg(x4 + r);
    const float4 xc = __ldg(x4 + c);
    const float  av = __ldg(ea + e);

    // stage tf32 row: [xr(4), xc(4), ea, 1, 0..0]
    {
        uint4* row = reinterpret_cast<uint4*>(&sA[(warp * 32 + lane) * ROWW]);
        row[0] = make_uint4(f2tf32(xr.x), f2tf32(xr.y), f2tf32(xr.z), f2tf32(xr.w));
        row[1] = make_uint4(f2tf32(xc.x), f2tf32(xc.y), f2tf32(xc.z), f2tf32(xc.w));
        row[2] = make_uint4(f2tf32(av), 0x3f800000u, 0u, 0u);
        row[3] = make_uint4(0u, 0u, 0u, 0u);
    }
    __syncwarp();

    // MMAs: D[h][nt] = 16x8 tile of H (h = edge half)
    float D[2][4][4];
    #pragma unroll
    for (int h = 0; h < 2; h++)
        #pragma unroll
        for (int nt = 0; nt < 4; nt++)
            #pragma unroll
            for (int q = 0; q < 4; q++) D[h][nt][q] = 0.0f;

    const unsigned* aw = &sA[warp * 32 * ROWW];
    #pragma unroll
    for (int h = 0; h < 2; h++) {
        #pragma unroll
        for (int kt = 0; kt < 2; kt++) {
            const unsigned a0 = aw[(h * 16 + grp)     * ROWW + kt * 8 + tig];
            const unsigned a1 = aw[(h * 16 + grp + 8) * ROWW + kt * 8 + tig];
            const unsigned a2 = aw[(h * 16 + grp)     * ROWW + kt * 8 + tig + 4];
            const unsigned a3 = aw[(h * 16 + grp + 8) * ROWW + kt * 8 + tig + 4];
            #pragma unroll
            for (int nt = 0; nt < 4; nt++)
                mma_tf32(D[h][nt], a0, a1, a2, a3, B0[kt][nt], B1[kt][nt]);
        }
    }

    // Epilogue: relu + project onto uc/um/us, quad-reduce, scatter
    const float sc = g_sc, sm = g_sm, ss = g_ss;
    #pragma unroll
    for (int h = 0; h < 2; h++) {
        float pcA = 0.f, pcB = 0.f, pmA = 0.f, pmB = 0.f, psA = 0.f, psB = 0.f;
        #pragma unroll
        for (int nt = 0; nt < 4; nt++) {
            const int c0 = nt * 8 + 2 * tig;
            const float u0 = suc[c0],  u1 = suc[c0 + 1];
            const float m0 = sum_[c0], m1 = sum_[c0 + 1];
            const float s0 = sus[c0],  s1 = sus[c0 + 1];
            const float h0 = fmaxf(D[h][nt][0], 0.f);  // (row grp,   col c0)
            const float h1 = fmaxf(D[h][nt][1], 0.f);  // (row grp,   col c0+1)
            const float h2 = fmaxf(D[h][nt][2], 0.f);  // (row grp+8, col c0)
            const float h3 = fmaxf(D[h][nt][3], 0.f);  // (row grp+8, col c0+1)
            pcA = fmaf(h0, u0, fmaf(h1, u1, pcA));
            pcB = fmaf(h2, u0, fmaf(h3, u1, pcB));
            pmA = fmaf(h0, m0, fmaf(h1, m1, pmA));
            pmB = fmaf(h2, m0, fmaf(h3, m1, pmB));
            psA = fmaf(h0, s0, fmaf(h1, s1, psA));
            psB = fmaf(h2, s0, fmaf(h3, s1, psB));
        }
        #pragma unroll
        for (int off = 1; off <= 2; off <<= 1) {
            pcA += __shfl_xor_sync(0xffffffffu, pcA, off);
            pcB += __shfl_xor_sync(0xffffffffu, pcB, off);
            pmA += __shfl_xor_sync(0xffffffffu, pmA, off);
            pmB += __shfl_xor_sync(0xffffffffu, pmB, off);
            psA += __shfl_xor_sync(0xffffffffu, psA, off);
            psB += __shfl_xor_sync(0xffffffffu, psB, off);
        }
        const int rA = __shfl_sync(0xffffffffu, r, h * 16 + grp);
        const int rB = __shfl_sync(0xffffffffu, r, h * 16 + grp + 8);
        if (tig == 0) {
            asm volatile("red.global.add.f32 [%0], %1;"
                         :: "l"(&g_accC[rA]), "f"(pcA + sc) : "memory");
            asm volatile("red.global.add.f32 [%0], %1;"
                         :: "l"(&g_accC[rB]), "f"(pcB + sc) : "memory");
            if (rA % NN >= NN - NF)
                asm volatile("red.global.add.v2.f32 [%0], {%1, %2};"
                             :: "l"(&g_accMS[rA]), "f"(pmA + sm), "f"(psA + ss) : "memory");
            if (rB % NN >= NN - NF)
                asm volatile("red.global.add.v2.f32 [%0], {%1, %2};"
                             :: "l"(&g_accMS[rB]), "f"(pmB + sm), "f"(psB + ss) : "memory");
        }
    }
}

// ---------------------------------------------------------------------------
// Kernel D: per-node heads + conc sum
// ---------------------------------------------------------------------------
__global__ __launch_bounds__(256) void node_kernel(
    const float* __restrict__ x,
    const float* __restrict__ Wc,  const float* __restrict__ bc,
    const float* __restrict__ Wmu, const float* __restrict__ bmu,
    const float* __restrict__ Wsig,const float* __restrict__ bsig,
    const float* __restrict__ high,
    float* __restrict__ out)
{
    __shared__ float sWarp[8];
    const int i = blockIdx.x * blockDim.x + threadIdx.x;

    float concv = 0.0f;
    if (i < N_NODES) {
        const float  ac = g_accC[i];
        const float4 xi = __ldg(reinterpret_cast<const float4*>(x) + i);

        const float craw = xi.x * __ldg(Wc+0) + xi.y * __ldg(Wc+1)
                         + xi.z * __ldg(Wc+2) + xi.w * __ldg(Wc+3)
                         + ac + __ldg(bc) + 1e-10f;
        concv = softplusf(craw);
        g_conc[i] = concv;

        const int p = i % NN;
        if (p >= NN - NF) {
            const float2 ms = g_accMS[i];
            const float mraw = xi.x * __ldg(Wmu+0) + xi.y * __ldg(Wmu+1)
                             + xi.z * __ldg(Wmu+2) + xi.w * __ldg(Wmu+3)
                             + ms.x + __ldg(bmu) + 1e-20f;
            const float sraw = xi.x * __ldg(Wsig+0) + xi.y * __ldg(Wsig+1)
                             + xi.z * __ldg(Wsig+2) + xi.w * __ldg(Wsig+3)
                             + ms.y + __ldg(bsig) + 1e-20f;
            const float alpha = softplusf(mraw) + 1e-20f;
            const float beta  = softplusf(sraw) + 1e-20f;
            const int g = i / NN;
            const int j = p - (NN - NF);
            out[g * OUT_C + NN + j] = alpha / (alpha + beta) * __ldg(high + j);
        }
    }

    float s = concv;
    #pragma unroll
    for (int off = 16; off > 0; off >>= 1) s += __shfl_xor_sync(0xffffffffu, s, off);
    if ((threadIdx.x & 31) == 0) sWarp[threadIdx.x >> 5] = s;
    __syncthreads();
    if (threadIdx.x == 0) {
        float tsum = 0.f;
        #pragma unroll
        for (int w = 0; w < 8; w++) tsum += sWarp[w];
        atomicAdd(&g_S, tsum);
    }
}

// ---------------------------------------------------------------------------
// Kernel E: normalize conc
// ---------------------------------------------------------------------------
__global__ void final_kernel(float* __restrict__ out) {
    const int i = blockIdx.x * blockDim.x + threadIdx.x;
    if (i >= N_NODES) return;
    const float invS = 1.0f / (g_S + 1e-20f);
    out[(i / NN) * OUT_C + (i % NN)] = g_conc[i] * invS;
}

// ---------------------------------------------------------------------------
extern "C" void kernel_launch(void* const* d_in, const int* in_sizes, int n_in,
                              void* d_out, int out_size) {
    const float* x    = (const float*)d_in[0];
    const void*  ei   = d_in[1];
    const float* ea   = (const float*)d_in[2];
    const float* high = (const float*)d_in[3];
    const float* W1   = (const float*)d_in[4];
    const float* b1   = (const float*)d_in[5];
    const float* W2   = (const float*)d_in[6];
    const float* b2   = (const float*)d_in[7];
    const float* Wc   = (const float*)d_in[8];
    const float* bc   = (const float*)d_in[9];
    const float* Wmu  = (const float*)d_in[10];
    const float* bmu  = (const float*)d_in[11];
    const float* Wsig = (const float*)d_in[12];
    const float* bsig = (const float*)d_in[13];
    float* out = (float*)d_out;

    prep_kernel<<<1, 32>>>((const int*)ei, W1, b1, W2, b2, Wc, Wmu, Wsig);
    zero_kernel<<<(N_NODES + 255) / 256, 256>>>();
    edge_kernel<<<N_EDGES / (32 * 8), 256>>>(x, ei, ea);   // 15625 blocks
    node_kernel<<<(N_NODES + 255) / 256, 256>>>(x, Wc, bc, Wmu, bmu, Wsig, bsig, high, out);
    final_kernel<<<(N_NODES + 255) / 256, 256>>>(out);
}

// round 9
// speedup vs baseline: 1.0164x; 1.0164x over previous
#include <cuda_runtime.h>
#include <cstdint>

#define N_NODES 250000
#define N_EDGES 4000000
#define NODE_F  4
#define HID     32
#define NN      50
#define NF      3
#define D_IN    9
#define OUT_C   53

// Scratch (device globals)
__device__ float  g_accC[N_NODES];                 // 1 MB
__device__ __align__(8) float2 g_accMS[N_NODES];   // 2 MB (tail nodes only)
__device__ float g_conc[N_NODES];
__device__ float g_S;
__device__ int   g_ei_is64;
__device__ float g_sc, g_sm, g_ss;                 // b2 . W*[4:36]
__device__ float g_uc[HID], g_um[HID], g_us[HID];  // W2 @ W*[4:36]
__device__ unsigned g_W1t[16 * HID];               // tf32 W1 padded to K=16 (row 9 = b1)

__device__ __forceinline__ float softplusf(float x) {
    return fmaxf(x, 0.0f) + log1pf(expf(-fabsf(x)));
}
__device__ __forceinline__ unsigned f2tf32(float f) {
    unsigned u; asm("cvt.rna.tf32.f32 %0, %1;" : "=r"(u) : "f"(f)); return u;
}
__device__ __forceinline__ void mma_tf32(float d[4],
                                         unsigned a0, unsigned a1, unsigned a2, unsigned a3,
                                         unsigned b0, unsigned b1) {
    asm("mma.sync.aligned.m16n8k8.row.col.f32.tf32.tf32.f32 "
        "{%0,%1,%2,%3}, {%4,%5,%6,%7}, {%8,%9}, {%0,%1,%2,%3};"
        : "+f"(d[0]), "+f"(d[1]), "+f"(d[2]), "+f"(d[3])
        : "r"(a0), "r"(a1), "r"(a2), "r"(a3), "r"(b0), "r"(b1));
}

// ---------------------------------------------------------------------------
// Kernel A: zero accumulators; block 0 additionally does prep (dtype detect,
// projections, tf32 W1). Merged so the whole pipeline is 4 launches/call.
// ---------------------------------------------------------------------------
__global__ void zero_prep_kernel(const int* __restrict__ ei32,
                                 const float* __restrict__ W1,
                                 const float* __restrict__ b1,
                                 const float* __restrict__ W2,
                                 const float* __restrict__ b2,
                                 const float* __restrict__ Wc,
                                 const float* __restrict__ Wmu,
                                 const float* __restrict__ Wsig)
{
    if (blockIdx.x == 0 && threadIdx.x < 32) {
        const int k = threadIdx.x;
        if (k == 0) {
            int z = 0;
            #pragma unroll
            for (int i = 1; i < 64; i += 2) z |= ei32[i];
            g_ei_is64 = (z == 0) ? 1 : 0;
            g_S = 0.0f;
        }
        float uc = 0.f, um = 0.f, us = 0.f;
        #pragma unroll
        for (int m = 0; m < HID; m++) {
            const float w = W2[k * HID + m];
            uc = fmaf(w, Wc[NODE_F + m],   uc);
            um = fmaf(w, Wmu[NODE_F + m],  um);
            us = fmaf(w, Wsig[NODE_F + m], us);
        }
        g_uc[k] = uc; g_um[k] = um; g_us[k] = us;

        #pragma unroll
        for (int d = 0; d < D_IN; d++) g_W1t[d * HID + k] = f2tf32(W1[d * HID + k]);
        g_W1t[9 * HID + k] = f2tf32(b1[k]);
        #pragma unroll
        for (int d = 10; d < 16; d++) g_W1t[d * HID + k] = 0u;

        float pc = b2[k] * Wc[NODE_F + k];
        float pm = b2[k] * Wmu[NODE_F + k];
        float ps = b2[k] * Wsig[NODE_F + k];
        #pragma unroll
        for (int off = 16; off > 0; off >>= 1) {
            pc += __shfl_xor_sync(0xffffffffu, pc, off);
            pm += __shfl_xor_sync(0xffffffffu, pm, off);
            ps += __shfl_xor_sync(0xffffffffu, ps, off);
        }
        if (k == 0) { g_sc = pc; g_sm = pm; g_ss = ps; }
    }

    const int i = (blockIdx.x == 0) ? -1 : (blockIdx.x - 1) * blockDim.x + threadIdx.x;
    if (i >= 0 && i < N_NODES) {
        g_accC[i] = 0.0f;
        if (i % NN >= NN - NF) g_accMS[i] = make_float2(0.f, 0.f);
    }
}

// ---------------------------------------------------------------------------
// Kernel B: tensor-core edge MLP. Warp handles 32 edges via tf32 m16n8k8 MMA.
// ---------------------------------------------------------------------------
#define ROWW 20   // padded SMEM row stride in words (80 B, conflict-free)

__global__ __launch_bounds__(256, 4) void edge_kernel(
    const float* __restrict__ x,
    const void* __restrict__ ei_raw,
    const float* __restrict__ ea)
{
    __shared__ unsigned sA[8 * 32 * ROWW];         // 20 KB staging
    __shared__ float suc[HID], sum_[HID], sus[HID];

    const int tid  = threadIdx.x;
    const int warp = tid >> 5;
    const int lane = tid & 31;
    const int grp  = lane >> 2;   // 0..7
    const int tig  = lane & 3;    // 0..3

    if (tid < HID) {
        suc[tid]  = g_uc[tid];
        sum_[tid] = g_um[tid];
        sus[tid]  = g_us[tid];
    }

    // B fragments: B[kt][nt] for H = A[32x16] @ W1t[16x32]
    unsigned B0[2][4], B1[2][4];
    #pragma unroll
    for (int kt = 0; kt < 2; kt++)
        #pragma unroll
        for (int nt = 0; nt < 4; nt++) {
            B0[kt][nt] = g_W1t[(kt * 8 + tig)     * HID + nt * 8 + grp];
            B1[kt][nt] = g_W1t[(kt * 8 + tig + 4) * HID + nt * 8 + grp];
        }
    __syncthreads();

    const int e = (blockIdx.x * 8 + warp) * 32 + lane;

    int r, c;
    if (g_ei_is64) {
        const long long* ei = (const long long*)ei_raw;
        r = (int)__ldg(ei + e);
        c = (int)__ldg(ei + N_EDGES + e);
    } else {
        const int* ei = (const int*)ei_raw;
        r = __ldg(ei + e);
        c = __ldg(ei + N_EDGES + e);
    }
    const float4* x4 = reinterpret_cast<const float4*>(x);
    const float4 xr = __ldg(x4 + r);
    const float4 xc = __ldg(x4 + c);
    const float  av = __ldg(ea + e);

    // stage tf32 row: [xr(4), xc(4), ea, 1, 0..0]
    {
        uint4* row = reinterpret_cast<uint4*>(&sA[(warp * 32 + lane) * ROWW]);
        row[0] = make_uint4(f2tf32(xr.x), f2tf32(xr.y), f2tf32(xr.z), f2tf32(xr.w));
        row[1] = make_uint4(f2tf32(xc.x), f2tf32(xc.y), f2tf32(xc.z), f2tf32(xc.w));
        row[2] = make_uint4(f2tf32(av), 0x3f800000u, 0u, 0u);
        row[3] = make_uint4(0u, 0u, 0u, 0u);
    }
    __syncwarp();

    // MMAs: D[h][nt] = 16x8 tile of H (h = edge half)
    float D[2][4][4];
    #pragma unroll
    for (int h = 0; h < 2; h++)
        #pragma unroll
        for (int nt = 0; nt < 4; nt++)
            #pragma unroll
            for (int q = 0; q < 4; q++) D[h][nt][q] = 0.0f;

    const unsigned* aw = &sA[warp * 32 * ROWW];
    #pragma unroll
    for (int h = 0; h < 2; h++) {
        #pragma unroll
        for (int kt = 0; kt < 2; kt++) {
            const unsigned a0 = aw[(h * 16 + grp)     * ROWW + kt * 8 + tig];
            const unsigned a1 = aw[(h * 16 + grp + 8) * ROWW + kt * 8 + tig];
            const unsigned a2 = aw[(h * 16 + grp)     * ROWW + kt * 8 + tig + 4];
            const unsigned a3 = aw[(h * 16 + grp + 8) * ROWW + kt * 8 + tig + 4];
            #pragma unroll
            for (int nt = 0; nt < 4; nt++)
                mma_tf32(D[h][nt], a0, a1, a2, a3, B0[kt][nt], B1[kt][nt]);
        }
    }

    // Epilogue: relu + project onto uc/um/us, quad-reduce, scatter
    const float sc = g_sc, sm = g_sm, ss = g_ss;
    #pragma unroll
    for (int h = 0; h < 2; h++) {
        float pcA = 0.f, pcB = 0.f, pmA = 0.f, pmB = 0.f, psA = 0.f, psB = 0.f;
        #pragma unroll
        for (int nt = 0; nt < 4; nt++) {
            const int c0 = nt * 8 + 2 * tig;
            const float u0 = suc[c0],  u1 = suc[c0 + 1];
            const float m0 = sum_[c0], m1 = sum_[c0 + 1];
            const float s0 = sus[c0],  s1 = sus[c0 + 1];
            const float h0 = fmaxf(D[h][nt][0], 0.f);
            const float h1 = fmaxf(D[h][nt][1], 0.f);
            const float h2 = fmaxf(D[h][nt][2], 0.f);
            const float h3 = fmaxf(D[h][nt][3], 0.f);
            pcA = fmaf(h0, u0, fmaf(h1, u1, pcA));
            pcB = fmaf(h2, u0, fmaf(h3, u1, pcB));
            pmA = fmaf(h0, m0, fmaf(h1, m1, pmA));
            pmB = fmaf(h2, m0, fmaf(h3, m1, pmB));
            psA = fmaf(h0, s0, fmaf(h1, s1, psA));
            psB = fmaf(h2, s0, fmaf(h3, s1, psB));
        }
        #pragma unroll
        for (int off = 1; off <= 2; off <<= 1) {
            pcA += __shfl_xor_sync(0xffffffffu, pcA, off);
            pcB += __shfl_xor_sync(0xffffffffu, pcB, off);
            pmA += __shfl_xor_sync(0xffffffffu, pmA, off);
            pmB += __shfl_xor_sync(0xffffffffu, pmB, off);
            psA += __shfl_xor_sync(0xffffffffu, psA, off);
            psB += __shfl_xor_sync(0xffffffffu, psB, off);
        }
        const int rA = __shfl_sync(0xffffffffu, r, h * 16 + grp);
        const int rB = __shfl_sync(0xffffffffu, r, h * 16 + grp + 8);
        if (tig == 0) {
            asm volatile("red.global.add.f32 [%0], %1;"
                         :: "l"(&g_accC[rA]), "f"(pcA + sc) : "memory");
            asm volatile("red.global.add.f32 [%0], %1;"
                         :: "l"(&g_accC[rB]), "f"(pcB + sc) : "memory");
            if (rA % NN >= NN - NF)
                asm volatile("red.global.add.v2.f32 [%0], {%1, %2};"
                             :: "l"(&g_accMS[rA]), "f"(pmA + sm), "f"(psA + ss) : "memory");
            if (rB % NN >= NN - NF)
                asm volatile("red.global.add.v2.f32 [%0], {%1, %2};"
                             :: "l"(&g_accMS[rB]), "f"(pmB + sm), "f"(psB + ss) : "memory");
        }
    }
}

// ---------------------------------------------------------------------------
// Kernel C: per-node heads + conc sum
// ---------------------------------------------------------------------------
__global__ __launch_bounds__(256) void node_kernel(
    const float* __restrict__ x,
    const float* __restrict__ Wc,  const float* __restrict__ bc,
    const float* __restrict__ Wmu, const float* __restrict__ bmu,
    const float* __restrict__ Wsig,const float* __restrict__ bsig,
    const float* __restrict__ high,
    float* __restrict__ out)
{
    __shared__ float sWarp[8];
    const int i = blockIdx.x * blockDim.x + threadIdx.x;

    float concv = 0.0f;
    if (i < N_NODES) {
        const float  ac = g_accC[i];
        const float4 xi = __ldg(reinterpret_cast<const float4*>(x) + i);

        const float craw = xi.x * __ldg(Wc+0) + xi.y * __ldg(Wc+1)
                         + xi.z * __ldg(Wc+2) + xi.w * __ldg(Wc+3)
                         + ac + __ldg(bc) + 1e-10f;
        concv = softplusf(craw);
        g_conc[i] = concv;

        const int p = i % NN;
        if (p >= NN - NF) {
            const float2 ms = g_accMS[i];
            const float mraw = xi.x * __ldg(Wmu+0) + xi.y * __ldg(Wmu+1)
                             + xi.z * __ldg(Wmu+2) + xi.w * __ldg(Wmu+3)
                             + ms.x + __ldg(bmu) + 1e-20f;
            const float sraw = xi.x * __ldg(Wsig+0) + xi.y * __ldg(Wsig+1)
                             + xi.z * __ldg(Wsig+2) + xi.w * __ldg(Wsig+3)
                             + ms.y + __ldg(bsig) + 1e-20f;
            const float alpha = softplusf(mraw) + 1e-20f;
            const float beta  = softplusf(sraw) + 1e-20f;
            const int g = i / NN;
            const int j = p - (NN - NF);
            out[g * OUT_C + NN + j] = alpha / (alpha + beta) * __ldg(high + j);
        }
    }

    float s = concv;
    #pragma unroll
    for (int off = 16; off > 0; off >>= 1) s += __shfl_xor_sync(0xffffffffu, s, off);
    if ((threadIdx.x & 31) == 0) sWarp[threadIdx.x >> 5] = s;
    __syncthreads();
    if (threadIdx.x == 0) {
        float tsum = 0.f;
        #pragma unroll
        for (int w = 0; w < 8; w++) tsum += sWarp[w];
        atomicAdd(&g_S, tsum);
    }
}

// ---------------------------------------------------------------------------
// Kernel D: normalize conc
// ---------------------------------------------------------------------------
__global__ void final_kernel(float* __restrict__ out) {
    const int i = blockIdx.x * blockDim.x + threadIdx.x;
    if (i >= N_NODES) return;
    const float invS = 1.0f / (g_S + 1e-20f);
    out[(i / NN) * OUT_C + (i % NN)] = g_conc[i] * invS;
}

// ---------------------------------------------------------------------------
extern "C" void kernel_launch(void* const* d_in, const int* in_sizes, int n_in,
                              void* d_out, int out_size) {
    const float* x    = (const float*)d_in[0];
    const void*  ei   = d_in[1];
    const float* ea   = (const float*)d_in[2];
    const float* high = (const float*)d_in[3];
    const float* W1   = (const float*)d_in[4];
    const float* b1   = (const float*)d_in[5];
    const float* W2   = (const float*)d_in[6];
    const float* b2   = (const float*)d_in[7];
    const float* Wc   = (const float*)d_in[8];
    const float* bc   = (const float*)d_in[9];
    const float* Wmu  = (const float*)d_in[10];
    const float* bmu  = (const float*)d_in[11];
    const float* Wsig = (const float*)d_in[12];
    const float* bsig = (const float*)d_in[13];
    float* out = (float*)d_out;

    zero_prep_kernel<<<(N_NODES + 255) / 256 + 1, 256>>>(
        (const int*)ei, W1, b1, W2, b2, Wc, Wmu, Wsig);
    edge_kernel<<<N_EDGES / (32 * 8), 256>>>(x, ei, ea);   // 15625 blocks
    node_kernel<<<(N_NODES + 255) / 256, 256>>>(x, Wc, bc, Wmu, bmu, Wsig, bsig, high, out);
    final_kernel<<<(N_NODES + 255) / 256, 256>>>(out);
}